// round 13
// baseline (speedup 1.0000x reference)
#include <cuda_runtime.h>
#include <cuda_fp16.h>
#include <cstdint>

#define BATCH_ 128
#define TLEN   256
#define HID    2048
#define FOURH  8192
#define NSTEP  255
#define BKC    128         // k per pipeline iteration (2 x 64 sub-tiles)
#define NCHUNK 16          // HID / BKC
#define NBLK   128         // 64 N-blocks (32 H-cols) x 2 M-blocks (64 rows)

// ---------------- persistent device state (no cudaMalloc allowed) -----------
__device__ float g_c[BATCH_ * HID];
__device__ __half g_h_hi[2][BATCH_ * HID];   // h quantized to fp16, double-buffered
// Wh^T, gate-permuted, fp16: p = nb*128 + w_n*64 + grp*32 + gate*8 + q
// maps to hcol = nb*32 + w_n*16 + grp*8 + q,  o = gate*HID + hcol
__device__ __half g_W_hi[(size_t)FOURH * HID];

// ---------------- helpers (all sm_80+ base-target PTX) ----------------------
__device__ __forceinline__ uint32_t sw128(uint32_t x) { return x ^ ((x >> 3) & 0x70); }

__device__ __forceinline__ uint32_t smem_u32(const void* p) {
    uint32_t a;
    asm("{ .reg .u64 t; cvta.to.shared.u64 t, %1; cvt.u32.u64 %0, t; }"
        : "=r"(a) : "l"(p));
    return a;
}

__device__ __forceinline__ void cp16(uint32_t d, const void* s) {
    asm volatile("cp.async.cg.shared.global [%0], [%1], 16;"
                 :: "r"(d), "l"(s) : "memory");
}

__device__ __forceinline__ void ldsm4(uint32_t* r, uint32_t a) {
    asm volatile("ldmatrix.sync.aligned.m8n8.x4.shared.b16 {%0,%1,%2,%3}, [%4];"
                 : "=r"(r[0]), "=r"(r[1]), "=r"(r[2]), "=r"(r[3]) : "r"(a));
}

__device__ __forceinline__ void mma16816(float* c, const uint32_t* a,
                                         uint32_t b0, uint32_t b1) {
    asm volatile(
        "mma.sync.aligned.m16n8k16.row.col.f32.f16.f16.f32 "
        "{%0,%1,%2,%3}, {%4,%5,%6,%7}, {%8,%9}, {%0,%1,%2,%3};"
        : "+f"(c[0]), "+f"(c[1]), "+f"(c[2]), "+f"(c[3])
        : "r"(a[0]), "r"(a[1]), "r"(a[2]), "r"(a[3]), "r"(b0), "r"(b1));
}

__device__ __forceinline__ float fast_sigmoid(float v) {
    return __fdividef(1.0f, 1.0f + __expf(-v));
}
__device__ __forceinline__ float fast_tanh(float v) {
    float a = fabsf(v);
    float t = __expf(-2.0f * a);
    float r = __fdividef(1.0f - t, 1.0f + t);
    return copysignf(r, v);
}

// smem stage (48KB): A sub0 8K | A sub1 8K | B sub0 16K | B sub1 16K
#define A_SUB  8192
#define B_BASE 16384
#define B_SUB  16384
#define STAGE_B 49152
#define NSTAGE 3
#define SMEM_TOTAL (NSTAGE * STAGE_B)   // 147456 per CTA; 1 CTA/SM

// ---------------- init: coalesced tiled transpose of Wh into fp16 -----------
__global__ __launch_bounds__(256) void init_w_kernel(const float* __restrict__ Wh) {
    __shared__ float tile[64][65];
    const int cb = blockIdx.x >> 5;        // 0..127  (p tile /64)
    const int kb = blockIdx.x & 31;        // 0..31   (k tile /64)
    const int tid = threadIdx.x;

    {
        const int k_local = tid >> 2;      // 0..63
        const int seg0 = tid & 3;
        const size_t krow = (size_t)(kb * 64 + k_local) * FOURH;
        #pragma unroll
        for (int ss = 0; ss < 2; ss++) {
            const int s = seg0 + ss * 4;   // 0..7: 8 consecutive permuted cols
            const int pbase = cb * 64 + s * 8;
            const int nb   = pbase >> 7;
            const int rr   = pbase & 127;
            const int w_n  = (rr >> 6) & 1;
            const int grp  = (rr >> 5) & 1;
            const int gate = (rr >> 3) & 3;
            const int o    = gate * HID + nb * 32 + w_n * 16 + grp * 8;
            const float4 v0 = *(const float4*)(Wh + krow + o);
            const float4 v1 = *(const float4*)(Wh + krow + o + 4);
            const int r0 = s * 8;
            tile[r0 + 0][k_local] = v0.x;
            tile[r0 + 1][k_local] = v0.y;
            tile[r0 + 2][k_local] = v0.z;
            tile[r0 + 3][k_local] = v0.w;
            tile[r0 + 4][k_local] = v1.x;
            tile[r0 + 5][k_local] = v1.y;
            tile[r0 + 6][k_local] = v1.z;
            tile[r0 + 7][k_local] = v1.w;
        }
    }
    __syncthreads();

    {
        const int r  = tid >> 2;           // 0..63
        const int k0 = (tid & 3) * 16;
        const size_t obase = (size_t)(cb * 64 + r) * HID + kb * 64 + k0;
        __half hibuf[16];
        #pragma unroll
        for (int i = 0; i < 16; i++)
            hibuf[i] = __float2half(tile[r][k0 + i]);
        *(uint4*)(g_W_hi + obase)     = *(uint4*)(hibuf);
        *(uint4*)(g_W_hi + obase + 8) = *(uint4*)(hibuf + 8);
    }
}

__global__ void zero_kernel() {
    const int n = BATCH_ * HID;
    for (int i = blockIdx.x * blockDim.x + threadIdx.x; i < n;
         i += gridDim.x * blockDim.x) {
        g_c[i] = 0.0f;
        g_h_hi[0][i] = __float2half(0.0f);
    }
}

// ---------------- one LSTM timestep ------------------------------------------
// z = h_fp16 @ W_fp16. Grid 128 = 64 N-blocks x 2 M-blocks; 1 CTA/SM.
// 128 threads = 4 warps, warp grid 2x2, warp tile m32 x n64 (deep HMMA ILP,
// 192 B LDS per mma). All 4 gates of each (row, hcol) stay in one thread.
__global__ __launch_bounds__(128, 1) void step_kernel(
    const float* __restrict__ x, const float* __restrict__ Wx,
    const float* __restrict__ bvec, int t)
{
    extern __shared__ __align__(1024) unsigned char smem[];
    const uint32_t sb = smem_u32(smem);
    const int tid  = threadIdx.x;
    const int w    = tid >> 5;
    const int lane = tid & 31;
    const int w_m  = w >> 1;          // 0..1 (row group of 32)
    const int w_n  = w & 1;           // 0..1 (col group of 64)
    const int nblk = blockIdx.x >> 1; // 0..63 (32 H-cols each)
    const int mblk = blockIdx.x & 1;
    const int row0 = mblk * 64;       // CTA's batch-row base

    const int par0 = t & 1;
    const int par1 = (t + 1) & 1;

    // -------- cp.async mappings: rows r0l + i*16, fixed k segment ------------
    const int r0l = tid >> 3;                 // 0..15
    const int kk0 = (tid & 7) * 8;            // 0..56
    const uint32_t so0 = sw128((uint32_t)r0l * 128 + kk0 * 2);  // +i*2048 per +16 rows
    const __half* __restrict__ pAh = g_h_hi[par0] + (size_t)(row0 + r0l) * HID + kk0;
    const __half* __restrict__ pBh = g_W_hi + (size_t)(nblk * 128 + r0l) * HID + kk0;
    const size_t rstep16 = (size_t)16 * HID;

    // -------- hoisted epilogue operands --------------------------------------
    const int q2 = (lane & 3) * 2;
    const int hcol0 = nblk * 32 + w_n * 16 + q2;   // grp adds +8
    float wx[2][4][2], bb[2][4][2];
    #pragma unroll
    for (int grp = 0; grp < 2; grp++)
        #pragma unroll
        for (int g = 0; g < 4; g++) {
            const int o = g * HID + hcol0 + grp * 8;
            wx[grp][g][0] = Wx[o];     wx[grp][g][1] = Wx[o + 1];
            bb[grp][g][0] = bvec[o];   bb[grp][g][1] = bvec[o + 1];
        }
    const int rbase = row0 + w_m * 32 + (lane >> 2);
    float xt[2][2];
    #pragma unroll
    for (int mt = 0; mt < 2; mt++)
        #pragma unroll
        for (int rh = 0; rh < 2; rh++)
            xt[mt][rh] = x[(rbase + mt * 16 + rh * 8) * TLEN + t];

    // -------- precomputed ldsm swizzled base offsets (region-relative) -------
    const int lm = lane & 15;
    const int lh = lane >> 4;
    const uint32_t kb_lane = (uint32_t)lh * 16;
    uint32_t roA[2], roB[4];
    #pragma unroll
    for (int mt = 0; mt < 2; mt++)
        roA[mt] = sw128((uint32_t)(w_m * 32 + mt * 16 + lm) * 128) ^ kb_lane;
    #pragma unroll
    for (int j = 0; j < 4; j++)
        roB[j] = sw128((uint32_t)(w_n * 64 + j * 16 + lm) * 128) ^ kb_lane;

    float cacc[2][2][4][4];   // [mt][grp][gate][frag]
    #pragma unroll
    for (int mt = 0; mt < 2; mt++)
        #pragma unroll
        for (int grp = 0; grp < 2; grp++)
            #pragma unroll
            for (int g = 0; g < 4; g++)
                #pragma unroll
                for (int i = 0; i < 4; i++) cacc[mt][grp][g][i] = 0.0f;

    // -------- chunk issue: A 4 + B 8 cp16 per sub-tile, 24 per thread --------
    auto issue_chunk = [&](uint32_t st, int c) {
        const int ko = c * BKC;
        #pragma unroll
        for (int s2 = 0; s2 < 2; s2++) {
            const int kof = ko + s2 * 64;
            const uint32_t sA = st + s2 * A_SUB;
            const uint32_t sB = st + B_BASE + s2 * B_SUB;
            #pragma unroll
            for (int i = 0; i < 4; i++)
                cp16(sA + so0 + i * 2048, pAh + kof + i * rstep16);
            #pragma unroll
            for (int i = 0; i < 8; i++)
                cp16(sB + so0 + i * 2048, pBh + kof + i * rstep16);
        }
        asm volatile("cp.async.commit_group;" ::: "memory");
    };

    // prologue: 2 chunks in flight (3 stages, skew 2)
    issue_chunk(sb, 0);
    issue_chunk(sb + STAGE_B, 1);

    uint32_t stage = 0;     // stage holding chunk c
    uint32_t stage2 = 2;    // stage to fill with chunk c+2
    #pragma unroll 1
    for (int c = 0; c < NCHUNK; c++) {
        if (c < NCHUNK - 1)
            asm volatile("cp.async.wait_group 1;" ::: "memory");
        else
            asm volatile("cp.async.wait_group 0;" ::: "memory");
        __syncthreads();

        if (c + 2 < NCHUNK)
            issue_chunk(sb + stage2 * STAGE_B, c + 2);

        const uint32_t st = sb + stage * STAGE_B;
        #pragma unroll
        for (int ks2 = 0; ks2 < 8; ks2++) {
            const int sub = ks2 >> 2;
            const uint32_t kx = (uint32_t)(ks2 & 3) * 32;
            const uint32_t sA = st + sub * A_SUB;
            const uint32_t sB = st + B_BASE + sub * B_SUB;
            uint32_t a[2][4], b[4][4];
            #pragma unroll
            for (int mt = 0; mt < 2; mt++)
                ldsm4(a[mt], sA + (roA[mt] ^ kx));
            #pragma unroll
            for (int j = 0; j < 4; j++)
                ldsm4(b[j], sB + (roB[j] ^ kx));
            #pragma unroll
            for (int mt = 0; mt < 2; mt++) {
                #pragma unroll
                for (int grp = 0; grp < 2; grp++) {
                    #pragma unroll
                    for (int g = 0; g < 4; g++) {
                        const int j = grp * 2 + (g >> 1), pr = g & 1;
                        mma16816(cacc[mt][grp][g], a[mt], b[j][pr], b[j][pr + 2]);
                    }
                }
            }
        }
        stage  = (stage == NSTAGE - 1) ? 0 : stage + 1;
        stage2 = (stage2 == NSTAGE - 1) ? 0 : stage2 + 1;
    }

    // ---- fused LSTM epilogue: all 4 gates of (row, hcol) in this thread ----
    #pragma unroll
    for (int mt = 0; mt < 2; mt++) {
        #pragma unroll
        for (int rh = 0; rh < 2; rh++) {
            const int row = rbase + mt * 16 + rh * 8;
            const float xv = xt[mt][rh];
            #pragma unroll
            for (int grp = 0; grp < 2; grp++) {
                const size_t base = (size_t)row * HID + hcol0 + grp * 8;
                const float2 cold = *(const float2*)(g_c + base);
                float hv[2], cv[2];
                #pragma unroll
                for (int e = 0; e < 2; e++) {
                    const int ri = rh * 2 + e;
                    const float zg = cacc[mt][grp][0][ri] + xv * wx[grp][0][e] + bb[grp][0][e];
                    const float zi = cacc[mt][grp][1][ri] + xv * wx[grp][1][e] + bb[grp][1][e];
                    const float zf = cacc[mt][grp][2][ri] + xv * wx[grp][2][e] + bb[grp][2][e];
                    const float zo = cacc[mt][grp][3][ri] + xv * wx[grp][3][e] + bb[grp][3][e];
                    const float gg = fast_tanh(zg);
                    const float ii = fast_sigmoid(zi);
                    const float ff = fast_sigmoid(zf);
                    const float oo = fast_sigmoid(zo);
                    const float co = (e == 0) ? cold.x : cold.y;
                    cv[e] = gg * ii + co * ff;
                    hv[e] = fast_tanh(cv[e]) * oo;
                }
                *(float2*)(g_c + base) = make_float2(cv[0], cv[1]);
                *(__half2*)(g_h_hi[par1] + base) =
                    __halves2half2(__float2half(hv[0]), __float2half(hv[1]));
            }
        }
    }
}

// ---------------- final projection + softmax ---------------------------------
__global__ void proj_kernel(const float* __restrict__ Wph,
                            const float* __restrict__ bp,
                            float* __restrict__ out)
{
    const int row = blockIdx.x;
    const int lane = threadIdx.x;
    const int par = NSTEP & 1;   // 1

    float acc = -1e30f;
    if (lane < 10) {
        acc = bp[lane];
        const size_t base = (size_t)row * HID;
        for (int k = 0; k < HID; k++) {
            acc += __half2float(g_h_hi[par][base + k]) * Wph[k * 10 + lane];
        }
    }
    float m = acc;
    #pragma unroll
    for (int off = 16; off > 0; off >>= 1)
        m = fmaxf(m, __shfl_xor_sync(0xffffffffu, m, off));
    float e = (lane < 10) ? __expf(acc - m) : 0.0f;
    float s = e;
    #pragma unroll
    for (int off = 16; off > 0; off >>= 1)
        s += __shfl_xor_sync(0xffffffffu, s, off);
    if (lane < 10) out[row * 10 + lane] = e / s;
}

extern "C" void kernel_launch(void* const* d_in, const int* in_sizes, int n_in,
                              void* d_out, int out_size) {
    (void)in_sizes; (void)n_in; (void)out_size;
    const float* x   = (const float*)d_in[0];
    const float* Wx  = (const float*)d_in[1];
    const float* Wh  = (const float*)d_in[2];
    const float* b   = (const float*)d_in[3];
    const float* Wph = (const float*)d_in[4];
    const float* bp  = (const float*)d_in[5];
    float* out = (float*)d_out;

    static int attr_set = 0;
    if (!attr_set) {
        cudaFuncSetAttribute(step_kernel,
                             cudaFuncAttributeMaxDynamicSharedMemorySize,
                             SMEM_TOTAL);
        attr_set = 1;
    }

    init_w_kernel<<<4096, 256>>>(Wh);
    zero_kernel<<<256, 256>>>();
    for (int t = 0; t < NSTEP; t++) {
        step_kernel<<<NBLK, 128, SMEM_TOTAL>>>(x, Wx, b, t);
    }
    proj_kernel<<<BATCH_, 32>>>(Wph, bp, out);
}

// round 14
// speedup vs baseline: 1.0467x; 1.0467x over previous
#include <cuda_runtime.h>
#include <cuda_fp16.h>
#include <cstdint>

#define BATCH_ 128
#define TLEN   256
#define HID    2048
#define FOURH  8192
#define NSTEP  255
#define BKC    128         // k per pipeline iteration (2 x 64 sub-tiles)
#define NCHUNK 16          // HID / BKC
#define NBLK   128         // one CTA per N-block of 64 permuted cols; full M=128

// ---------------- persistent device state (no cudaMalloc allowed) -----------
__device__ float g_c[BATCH_ * HID];
__device__ __half g_h_hi[2][BATCH_ * HID];   // h quantized to fp16, double-buffered
// Wh^T, gate-permuted, fp16: permuted col p = nb*64 + w_n*32 + gate*8 + q
// maps to hcol = nb*16 + w_n*8 + q,  o = gate*HID + hcol
__device__ __half g_W_hi[(size_t)FOURH * HID];

// ---------------- helpers (all sm_80+ base-target PTX) ----------------------
__device__ __forceinline__ uint32_t sw128(uint32_t x) { return x ^ ((x >> 3) & 0x70); }

__device__ __forceinline__ uint32_t smem_u32(const void* p) {
    uint32_t a;
    asm("{ .reg .u64 t; cvta.to.shared.u64 t, %1; cvt.u32.u64 %0, t; }"
        : "=r"(a) : "l"(p));
    return a;
}

__device__ __forceinline__ void cp16(uint32_t d, const void* s) {
    asm volatile("cp.async.cg.shared.global [%0], [%1], 16;"
                 :: "r"(d), "l"(s) : "memory");
}

__device__ __forceinline__ void ldsm4(uint32_t* r, uint32_t a) {
    asm volatile("ldmatrix.sync.aligned.m8n8.x4.shared.b16 {%0,%1,%2,%3}, [%4];"
                 : "=r"(r[0]), "=r"(r[1]), "=r"(r[2]), "=r"(r[3]) : "r"(a));
}

__device__ __forceinline__ void mma16816(float* c, const uint32_t* a,
                                         uint32_t b0, uint32_t b1) {
    asm volatile(
        "mma.sync.aligned.m16n8k16.row.col.f32.f16.f16.f32 "
        "{%0,%1,%2,%3}, {%4,%5,%6,%7}, {%8,%9}, {%0,%1,%2,%3};"
        : "+f"(c[0]), "+f"(c[1]), "+f"(c[2]), "+f"(c[3])
        : "r"(a[0]), "r"(a[1]), "r"(a[2]), "r"(a[3]), "r"(b0), "r"(b1));
}

__device__ __forceinline__ float fast_sigmoid(float v) {
    return __fdividef(1.0f, 1.0f + __expf(-v));
}
__device__ __forceinline__ float fast_tanh(float v) {
    float a = fabsf(v);
    float t = __expf(-2.0f * a);
    float r = __fdividef(1.0f - t, 1.0f + t);
    return copysignf(r, v);
}

// smem stage (48KB): A sub0 16K | A sub1 16K | B sub0 8K | B sub1 8K
#define A_SUB  16384
#define B_BASE 32768
#define B_SUB  8192
#define STAGE_B 49152
#define NSTAGE 3
#define SMEM_TOTAL (NSTAGE * STAGE_B)   // 147456 per CTA; 1 CTA/SM

// ---------------- init: coalesced tiled transpose of Wh into fp16 -----------
// (same permutation as the best R10 kernel: r = w_n*32 + gate*8 + q per 64-col block)
__global__ __launch_bounds__(256) void init_w_kernel(const float* __restrict__ Wh) {
    __shared__ float tile[64][65];
    const int cb = blockIdx.x >> 5;        // 0..127  (p tile /64 == nblk)
    const int kb = blockIdx.x & 31;        // 0..31   (k tile /64)
    const int tid = threadIdx.x;

    {
        const int k_local = tid >> 2;      // 0..63
        const int seg0 = tid & 3;
        const size_t krow = (size_t)(kb * 64 + k_local) * FOURH;
        #pragma unroll
        for (int ss = 0; ss < 2; ss++) {
            const int s = seg0 + ss * 4;   // 0..7
            const int w_n = s >> 2;
            const int gate = s & 3;
            const int base_o = gate * HID + cb * 16 + w_n * 8;
            const float4 v0 = *(const float4*)(Wh + krow + base_o);
            const float4 v1 = *(const float4*)(Wh + krow + base_o + 4);
            const int r0 = w_n * 32 + gate * 8;
            tile[r0 + 0][k_local] = v0.x;
            tile[r0 + 1][k_local] = v0.y;
            tile[r0 + 2][k_local] = v0.z;
            tile[r0 + 3][k_local] = v0.w;
            tile[r0 + 4][k_local] = v1.x;
            tile[r0 + 5][k_local] = v1.y;
            tile[r0 + 6][k_local] = v1.z;
            tile[r0 + 7][k_local] = v1.w;
        }
    }
    __syncthreads();

    {
        const int r  = tid >> 2;           // 0..63
        const int k0 = (tid & 3) * 16;
        const size_t obase = (size_t)(cb * 64 + r) * HID + kb * 64 + k0;
        __half hibuf[16];
        #pragma unroll
        for (int i = 0; i < 16; i++)
            hibuf[i] = __float2half(tile[r][k0 + i]);
        *(uint4*)(g_W_hi + obase)     = *(uint4*)(hibuf);
        *(uint4*)(g_W_hi + obase + 8) = *(uint4*)(hibuf + 8);
    }
}

__global__ void zero_kernel() {
    const int n = BATCH_ * HID;
    for (int i = blockIdx.x * blockDim.x + threadIdx.x; i < n;
         i += gridDim.x * blockDim.x) {
        g_c[i] = 0.0f;
        g_h_hi[0][i] = __float2half(0.0f);
    }
}

// ---------------- one LSTM timestep ------------------------------------------
// z = h_fp16 @ W_fp16. Grid 128 = 128 N-blocks (full M per CTA); 1 CTA/SM.
// 256 threads = 8 warps, warp grid 4x2 of m32n32. Register fragment
// double-buffering: ldsm for k-step ks+1 issued before the mma block of ks.
__global__ __launch_bounds__(256, 1) void step_kernel(
    const float* __restrict__ x, const float* __restrict__ Wx,
    const float* __restrict__ bvec, int t)
{
    extern __shared__ __align__(1024) unsigned char smem[];
    const uint32_t sb = smem_u32(smem);
    const int tid  = threadIdx.x;
    const int w    = tid >> 5;
    const int lane = tid & 31;
    const int w_m  = w >> 1;          // 0..3 (row group of 32)
    const int w_n  = w & 1;           // 0..1 (col group of 32)
    const int nblk = blockIdx.x;      // 0..127 (16 H-cols each)

    const int par0 = t & 1;
    const int par1 = (t + 1) & 1;

    // -------- cp.async mappings: rows r0l + i*32, fixed k segment ------------
    const int r0l = tid >> 3;                 // 0..31
    const int kk0 = (tid & 7) * 8;            // 0..56
    const uint32_t so0 = sw128((uint32_t)r0l * 128 + kk0 * 2);  // +4096 per +32 rows
    const __half* __restrict__ pAh = g_h_hi[par0] + (size_t)r0l * HID + kk0;
    const __half* __restrict__ pBh = g_W_hi + (size_t)(nblk * 64 + r0l) * HID + kk0;
    const size_t rstep32 = (size_t)32 * HID;

    // -------- hoisted epilogue operands --------------------------------------
    const int q2 = (lane & 3) * 2;
    const int hcol0 = nblk * 16 + w_n * 8 + q2;
    float wx[4][2], bb[4][2];
    #pragma unroll
    for (int g = 0; g < 4; g++) {
        const int o = g * HID + hcol0;
        wx[g][0] = Wx[o];     wx[g][1] = Wx[o + 1];
        bb[g][0] = bvec[o];   bb[g][1] = bvec[o + 1];
    }
    const int rbase = w_m * 32 + (lane >> 2);
    float xt[2][2];
    #pragma unroll
    for (int mt = 0; mt < 2; mt++)
        #pragma unroll
        for (int rh = 0; rh < 2; rh++)
            xt[mt][rh] = x[(rbase + mt * 16 + rh * 8) * TLEN + t];

    // -------- precomputed ldsm swizzled base offsets (region-relative) -------
    const int lm = lane & 15;
    const int lh = lane >> 4;
    const uint32_t kb_lane = (uint32_t)lh * 16;
    uint32_t roA[2], roB[2];
    #pragma unroll
    for (int mt = 0; mt < 2; mt++)
        roA[mt] = sw128((uint32_t)(w_m * 32 + mt * 16 + lm) * 128) ^ kb_lane;
    #pragma unroll
    for (int gg = 0; gg < 2; gg++)
        roB[gg] = sw128((uint32_t)(w_n * 32 + gg * 16 + lm) * 128) ^ kb_lane;

    float cacc[2][4][4];
    #pragma unroll
    for (int mt = 0; mt < 2; mt++)
        #pragma unroll
        for (int g = 0; g < 4; g++)
            #pragma unroll
            for (int i = 0; i < 4; i++) cacc[mt][g][i] = 0.0f;

    // -------- chunk issue: A 8 + B 4 cp16 per chunk (K=128) ------------------
    auto issue_chunk = [&](uint32_t st, int c) {
        const int ko = c * BKC;
        #pragma unroll
        for (int s2 = 0; s2 < 2; s2++) {
            const int kof = ko + s2 * 64;
            const uint32_t sA = st + s2 * A_SUB;
            const uint32_t sB = st + B_BASE + s2 * B_SUB;
            #pragma unroll
            for (int i = 0; i < 4; i++)
                cp16(sA + so0 + i * 4096, pAh + kof + i * rstep32);
            cp16(sB + so0, pBh + kof);
            cp16(sB + so0 + 4096, pBh + kof + rstep32);
        }
        asm volatile("cp.async.commit_group;" ::: "memory");
    };

    // prologue: 2 chunks in flight (3 stages, skew 2)
    issue_chunk(sb, 0);
    issue_chunk(sb + STAGE_B, 1);

    uint32_t stage = 0;     // stage holding chunk c
    uint32_t stage2 = 2;    // stage to fill with chunk c+2
    #pragma unroll 1
    for (int c = 0; c < NCHUNK; c++) {
        if (c < NCHUNK - 1)
            asm volatile("cp.async.wait_group 1;" ::: "memory");
        else
            asm volatile("cp.async.wait_group 0;" ::: "memory");
        __syncthreads();

        if (c + 2 < NCHUNK)
            issue_chunk(sb + stage2 * STAGE_B, c + 2);

        const uint32_t st = sb + stage * STAGE_B;

        // register fragment double-buffering across the 8 k16-steps
        uint32_t a[2][2][4], b[2][2][4];   // [buf][tile][frag]
        auto ldfrag = [&](int buf, int ksn) {
            const uint32_t sA = st + (uint32_t)(ksn >> 2) * A_SUB;
            const uint32_t sB = st + B_BASE + (uint32_t)(ksn >> 2) * B_SUB;
            const uint32_t kx = (uint32_t)(ksn & 3) * 32;
            #pragma unroll
            for (int mt = 0; mt < 2; mt++)
                ldsm4(a[buf][mt], sA + (roA[mt] ^ kx));
            #pragma unroll
            for (int gg = 0; gg < 2; gg++)
                ldsm4(b[buf][gg], sB + (roB[gg] ^ kx));
        };

        ldfrag(0, 0);
        #pragma unroll
        for (int ks = 0; ks < 8; ks++) {
            const int cur = ks & 1;
            if (ks < 7) ldfrag(cur ^ 1, ks + 1);
            #pragma unroll
            for (int mt = 0; mt < 2; mt++) {
                #pragma unroll
                for (int g = 0; g < 4; g++) {
                    const int gg = g >> 1, pr = g & 1;
                    mma16816(cacc[mt][g], a[cur][mt],
                             b[cur][gg][pr], b[cur][gg][pr + 2]);
                }
            }
        }
        stage  = (stage == NSTAGE - 1) ? 0 : stage + 1;
        stage2 = (stage2 == NSTAGE - 1) ? 0 : stage2 + 1;
    }

    // ---- fused LSTM epilogue: all 4 gates of (row, hcol) in this thread ----
    #pragma unroll
    for (int mt = 0; mt < 2; mt++) {
        #pragma unroll
        for (int rh = 0; rh < 2; rh++) {
            const int row = rbase + mt * 16 + rh * 8;
            const float xv = xt[mt][rh];
            const size_t base = (size_t)row * HID + hcol0;
            const float2 cold = *(const float2*)(g_c + base);
            float hv[2], cv[2];
            #pragma unroll
            for (int e = 0; e < 2; e++) {
                const int ri = rh * 2 + e;
                const float zg = cacc[mt][0][ri] + xv * wx[0][e] + bb[0][e];
                const float zi = cacc[mt][1][ri] + xv * wx[1][e] + bb[1][e];
                const float zf = cacc[mt][2][ri] + xv * wx[2][e] + bb[2][e];
                const float zo = cacc[mt][3][ri] + xv * wx[3][e] + bb[3][e];
                const float gg = fast_tanh(zg);
                const float ii = fast_sigmoid(zi);
                const float ff = fast_sigmoid(zf);
                const float oo = fast_sigmoid(zo);
                const float co = (e == 0) ? cold.x : cold.y;
                cv[e] = gg * ii + co * ff;
                hv[e] = fast_tanh(cv[e]) * oo;
            }
            *(float2*)(g_c + base) = make_float2(cv[0], cv[1]);
            *(__half2*)(g_h_hi[par1] + base) =
                __halves2half2(__float2half(hv[0]), __float2half(hv[1]));
        }
    }
}

// ---------------- final projection + softmax ---------------------------------
__global__ void proj_kernel(const float* __restrict__ Wph,
                            const float* __restrict__ bp,
                            float* __restrict__ out)
{
    const int row = blockIdx.x;
    const int lane = threadIdx.x;
    const int par = NSTEP & 1;   // 1

    float acc = -1e30f;
    if (lane < 10) {
        acc = bp[lane];
        const size_t base = (size_t)row * HID;
        for (int k = 0; k < HID; k++) {
            acc += __half2float(g_h_hi[par][base + k]) * Wph[k * 10 + lane];
        }
    }
    float m = acc;
    #pragma unroll
    for (int off = 16; off > 0; off >>= 1)
        m = fmaxf(m, __shfl_xor_sync(0xffffffffu, m, off));
    float e = (lane < 10) ? __expf(acc - m) : 0.0f;
    float s = e;
    #pragma unroll
    for (int off = 16; off > 0; off >>= 1)
        s += __shfl_xor_sync(0xffffffffu, s, off);
    if (lane < 10) out[row * 10 + lane] = e / s;
}

extern "C" void kernel_launch(void* const* d_in, const int* in_sizes, int n_in,
                              void* d_out, int out_size) {
    (void)in_sizes; (void)n_in; (void)out_size;
    const float* x   = (const float*)d_in[0];
    const float* Wx  = (const float*)d_in[1];
    const float* Wh  = (const float*)d_in[2];
    const float* b   = (const float*)d_in[3];
    const float* Wph = (const float*)d_in[4];
    const float* bp  = (const float*)d_in[5];
    float* out = (float*)d_out;

    static int attr_set = 0;
    if (!attr_set) {
        cudaFuncSetAttribute(step_kernel,
                             cudaFuncAttributeMaxDynamicSharedMemorySize,
                             SMEM_TOTAL);
        attr_set = 1;
    }

    init_w_kernel<<<4096, 256>>>(Wh);
    zero_kernel<<<256, 256>>>();
    for (int t = 0; t < NSTEP; t++) {
        step_kernel<<<NBLK, 256, SMEM_TOTAL>>>(x, Wx, b, t);
    }
    proj_kernel<<<BATCH_, 32>>>(Wph, bp, out);
}